// round 3
// baseline (speedup 1.0000x reference)
#include <cuda_runtime.h>
#include <cstdint>

// ---------------------------------------------------------------------------
// HexagonalSensor: 16.7M photons -> hex-pixel scatter add (1801 bins)
// R3: packed f32x2 math front-end (2 photons/instr), zero fused into hex
// (per-CTA private column), REDG privatized scatter, flat-index bound check.
// ---------------------------------------------------------------------------

#define NCTA 592          // 4 CTAs per SM
#define TPB  256
#define MAX_PIX 2048

// scratch[pix * NCTA + cta]  (pix-major so reduce reads contiguous)
__device__ float g_scratch[MAX_PIX * NCTA];

typedef unsigned long long u64;

// ------------------------ f32x2 packed helpers -----------------------------
__device__ __forceinline__ u64 pk2(float lo, float hi) {
    u64 d; asm("mov.b64 %0, {%1, %2};" : "=l"(d) : "f"(lo), "f"(hi)); return d;
}
__device__ __forceinline__ u64 bc2(float v) { return pk2(v, v); }
__device__ __forceinline__ float2 up2(u64 v) {
    float2 f;
    asm("mov.b64 {%0, %1}, %2;" : "=f"(f.x), "=f"(f.y) : "l"(v));
    return f;
}
__device__ __forceinline__ u64 fadd2(u64 a, u64 b) {
    u64 d; asm("add.rn.f32x2 %0, %1, %2;" : "=l"(d) : "l"(a), "l"(b)); return d;
}
__device__ __forceinline__ u64 fmul2(u64 a, u64 b) {
    u64 d; asm("mul.rn.f32x2 %0, %1, %2;" : "=l"(d) : "l"(a), "l"(b)); return d;
}
__device__ __forceinline__ u64 ffma2(u64 a, u64 b, u64 c) {
    u64 d; asm("fma.rn.f32x2 %0, %1, %2, %3;" : "=l"(d) : "l"(a), "l"(b), "l"(c)); return d;
}

// ------------------------ per-photon scalar tail ---------------------------
__device__ __forceinline__ void photon_tail(
    float dq, float dr, float ds,
    float qr, float rr, float nrs, float nqs,
    float v, float Cq, float Cr,
    int dim, unsigned dim2, unsigned C0,
    const int* __restrict__ s_lut,
    float* __restrict__ my_col)
{
    // cube-round fixup decision (FSETP folds the abs as operand modifiers)
    bool cq = (fabsf(dq) > fabsf(dr)) & (fabsf(dq) > fabsf(ds));
    bool cr = (fabsf(dr) > fabsf(dq)) & (fabsf(dr) > fabsf(ds));
    float qv = cq ? nrs : qr;        // -(rr+sr) when q gets fixed
    float rv = cr ? nqs : rr;        // -(qr+sr) when r gets fixed

    // magic rebase: qv + (MAG - qmin) puts q_idx in the low mantissa bits.
    // Fold the MAGBITS removal into the flat index via mod-2^32 arithmetic.
    unsigned Qm = (unsigned)__float_as_int(qv + Cq);
    unsigned Rm = (unsigned)__float_as_int(rv + Cr);
    unsigned flat = Qm * (unsigned)dim + (Rm + C0);  // == q_idx*dim + r_idx

    int pix = (flat < dim2) ? s_lut[flat] : -1;
    if (pix >= 0)
        atomicAdd(my_col + (unsigned)pix * NCTA, v);  // -> RED.E.ADD.F32
}

// ------------------------------- hex ---------------------------------------
__global__ __launch_bounds__(TPB)
void hex_kernel(const float* __restrict__ x,
                const float* __restrict__ y,
                const float* __restrict__ vals,
                const int* __restrict__ lut,
                const float* __restrict__ p_hs,
                const float* __restrict__ p_rot,
                const float* __restrict__ p_ox,
                const float* __restrict__ p_oy,
                const int* __restrict__ p_qmin,
                const int* __restrict__ p_rmin,
                int n4, int dim, int npix)
{
    __shared__ int s_lut[2448];    // 49*49 = 2401

    // --- zero this CTA's private scratch column (no cross-CTA hazard) ---
    float* my_col = g_scratch + blockIdx.x;
    for (int p = threadIdx.x; p < npix; p += TPB)
        my_col[(unsigned)p * NCTA] = 0.0f;

    for (int i = threadIdx.x; i < dim * dim; i += TPB)
        s_lut[i] = lut[i];

    float hs  = *p_hs;
    float rot = *p_rot;
    float ox  = *p_ox;
    float oy  = *p_oy;
    int qmin  = *p_qmin;
    int rmin  = *p_rmin;

    float ca = cosf(-rot), sa = sinf(-rot);
    float inv_hs = 1.0f / hs;
    float c1v =  0.57735026919f * inv_hs;
    float c2v = -0.33333333333f * inv_hs;
    float c3v =  0.66666666667f * inv_hs;

    const float MAG = 12582912.0f;            // 1.5 * 2^23
    const unsigned MAGBITS = 0x4B400000u;
    float Cq = MAG - (float)qmin;
    float Cr = MAG - (float)rmin;
    unsigned dim2 = (unsigned)(dim * dim);
    unsigned C0 = 0u - MAGBITS * (unsigned)(dim + 1);  // mod 2^32 fold

    // packed broadcast constants
    u64 nOx2 = bc2(-ox),  nOy2 = bc2(-oy);
    u64 ca2  = bc2(ca),   sa2  = bc2(sa),  nsa2 = bc2(-sa);
    u64 c12  = bc2(c1v),  c22  = bc2(c2v), c32  = bc2(c3v);
    u64 MAG2 = bc2(MAG),  nMAG2 = bc2(-MAG), n1 = bc2(-1.0f);

    __threadfence();       // zeros globally visible before any RED
    __syncthreads();

    const float4* x4 = reinterpret_cast<const float4*>(x);
    const float4* y4 = reinterpret_cast<const float4*>(y);
    const float4* v4 = reinterpret_cast<const float4*>(vals);

    int stride = gridDim.x * blockDim.x;
    for (int i = blockIdx.x * blockDim.x + threadIdx.x; i < n4; i += stride) {
        float4 xx = __ldcs(&x4[i]);      // streaming: don't evict scratch/L2
        float4 yy = __ldcs(&y4[i]);
        float4 vv = __ldcs(&v4[i]);

        #pragma unroll
        for (int h = 0; h < 2; h++) {
            float xa = h ? xx.z : xx.x, xb = h ? xx.w : xx.y;
            float ya = h ? yy.z : yy.x, yb = h ? yy.w : yy.y;
            float va = h ? vv.z : vv.x, vb = h ? vv.w : vv.y;

            // --- packed front-end: 2 photons per instruction ---
            u64 X  = pk2(xa, xb),        Y  = pk2(ya, yb);
            u64 xs = fadd2(X, nOx2);
            u64 ys = fadd2(Y, nOy2);
            u64 xr = ffma2(ca2, xs, fmul2(nsa2, ys));
            u64 yr = ffma2(sa2, xs, fmul2(ca2,  ys));
            u64 q  = ffma2(c12, xr, fmul2(c22, yr));
            u64 r  = fmul2(c32, yr);
            u64 qpr= fadd2(q, r);                  // q + r = -s
            u64 fq = fadd2(q, MAG2);
            u64 fr = fadd2(r, MAG2);
            u64 fs = ffma2(qpr, n1, MAG2);         // MAG - (q+r)
            u64 qr = fadd2(fq, nMAG2);             // round_half_even(q)
            u64 rr = fadd2(fr, nMAG2);
            u64 sr = fadd2(fs, nMAG2);
            u64 dq = ffma2(q, n1, qr);             // qr - q
            u64 dr = ffma2(r, n1, rr);
            u64 ds = fadd2(sr, qpr);               // sr - s
            u64 nrs= ffma2(fadd2(rr, sr), n1, bc2(0.0f));  // -(rr+sr)
            u64 nqs= ffma2(fadd2(qr, sr), n1, bc2(0.0f));  // -(qr+sr)

            float2 Dq = up2(dq), Dr = up2(dr), Ds = up2(ds);
            float2 Qr = up2(qr), Rr = up2(rr);
            float2 Nrs = up2(nrs), Nqs = up2(nqs);

            photon_tail(Dq.x, Dr.x, Ds.x, Qr.x, Rr.x, Nrs.x, Nqs.x,
                        va, Cq, Cr, dim, dim2, C0, s_lut, my_col);
            photon_tail(Dq.y, Dr.y, Ds.y, Qr.y, Rr.y, Nrs.y, Nqs.y,
                        vb, Cq, Cr, dim, dim2, C0, s_lut, my_col);
        }
    }
}

// ------------------------------ reduce -------------------------------------
__global__ void reduce_kernel(float* __restrict__ out, int npix) {
    int p = blockIdx.x * blockDim.x + threadIdx.x;
    if (p >= npix) return;
    const float4* row = reinterpret_cast<const float4*>(g_scratch + (size_t)p * NCTA);
    float s0 = 0.f, s1 = 0.f, s2 = 0.f, s3 = 0.f;
    #pragma unroll 4
    for (int c = 0; c < NCTA / 4; c++) {
        float4 t = row[c];
        s0 += t.x; s1 += t.y; s2 += t.z; s3 += t.w;
    }
    out[p] = (s0 + s1) + (s2 + s3);
}

// ------------------------------ launch -------------------------------------
extern "C" void kernel_launch(void* const* d_in, const int* in_sizes, int n_in,
                              void* d_out, int out_size)
{
    const float* x    = (const float*)d_in[0];
    const float* y    = (const float*)d_in[1];
    const float* vals = (const float*)d_in[2];
    const int*   lut  = (const int*)  d_in[3];
    const float* hs   = (const float*)d_in[4];
    const float* rot  = (const float*)d_in[5];
    const float* ox   = (const float*)d_in[6];
    const float* oy   = (const float*)d_in[7];
    const int*   qmin = (const int*)  d_in[8];
    const int*   rmin = (const int*)  d_in[9];

    int n = in_sizes[0];
    int lutsize = in_sizes[3];
    int dim = 1;
    while (dim * dim < lutsize) dim++;   // 49

    int npix = out_size;                 // 1801
    if (npix > MAX_PIX) npix = MAX_PIX;

    hex_kernel<<<NCTA, TPB>>>(x, y, vals, lut, hs, rot, ox, oy,
                              qmin, rmin, n / 4, dim, npix);
    reduce_kernel<<<(npix + 127) / 128, 128>>>((float*)d_out, npix);
}

// round 4
// speedup vs baseline: 1.6260x; 1.6260x over previous
#include <cuda_runtime.h>
#include <cstdint>

// ---------------------------------------------------------------------------
// HexagonalSensor: 16.7M photons -> hex-pixel scatter add (1801 bins)
// R4: revert hex to R2 scalar form (f32x2 regressed); two-stage warp reduce
// (was 29.7us latency-bound, now ~4us); 4-launch layout so ncu (-s 5) lands
// on hex_kernel.
// ---------------------------------------------------------------------------

#define NCTA 592          // 4 CTAs per SM
#define TPB  256
#define MAX_PIX 2048
#define QUARTER (NCTA / 4)   // 148

// scratch[pix * NCTA + cta]  (pix-major so reduce reads contiguous)
__device__ float g_scratch[MAX_PIX * NCTA];
__device__ float g_partial[MAX_PIX * 4];

// -------------------------- zero scratch -----------------------------------
__global__ void zero_kernel(int total4) {
    float4* p = reinterpret_cast<float4*>(g_scratch);
    float4 z = make_float4(0.f, 0.f, 0.f, 0.f);
    for (int i = blockIdx.x * blockDim.x + threadIdx.x; i < total4;
         i += gridDim.x * blockDim.x)
        p[i] = z;
}

// -------------------------- main histogram ---------------------------------
__device__ __forceinline__ void photon_one(
    float x, float y, float v,
    float ca, float sa, float ox, float oy,
    float c1, float c2, float c3,
    int qmin, int rmin, int dim,
    const int* __restrict__ s_lut,
    float* __restrict__ my_col)
{
    // rotate into grid frame
    float xs = x - ox;
    float ys = y - oy;
    float xrot = fmaf(ca, xs, -(sa * ys));
    float yrot = fmaf(sa, xs, ca * ys);

    // cartesian -> axial (constants folded with 1/hex_size)
    float q = fmaf(c1, xrot, c2 * yrot);
    float r = c3 * yrot;
    float s = -q - r;

    // round-half-even via magic add; integer falls out of mantissa bits
    const float MAG = 12582912.0f;           // 1.5 * 2^23
    const int   MAGBITS = 0x4B400000;
    float fq = q + MAG, fr = r + MAG, fs = s + MAG;
    float qr = fq - MAG, rr = fr - MAG, sr = fs - MAG;
    int qi = __float_as_int(fq) - MAGBITS;
    int ri = __float_as_int(fr) - MAGBITS;
    int si = __float_as_int(fs) - MAGBITS;

    // cube-round fixup (faithful to reference _axial_round)
    float qd = fabsf(qr - q), rd = fabsf(rr - r), sd = fabsf(sr - s);
    bool cq = (qd > rd) && (qd > sd);
    bool cr = (rd > qd) && (rd > sd);
    if (cq)      qi = -ri - si;
    else if (cr) ri = -qi - si;

    int q_idx = qi - qmin;
    int r_idx = ri - rmin;
    bool inb = ((unsigned)q_idx < (unsigned)dim) &
               ((unsigned)r_idx < (unsigned)dim);
    int pix = -1;
    if (inb) pix = s_lut[q_idx * dim + r_idx];
    if (pix >= 0) {
        // unused return -> RED.E.ADD.F32 (fire-and-forget to L2)
        atomicAdd(my_col + (size_t)pix * NCTA, v);
    }
}

__global__ __launch_bounds__(TPB)
void hex_kernel(const float* __restrict__ x,
                const float* __restrict__ y,
                const float* __restrict__ vals,
                const int* __restrict__ lut,
                const float* __restrict__ p_hs,
                const float* __restrict__ p_rot,
                const float* __restrict__ p_ox,
                const float* __restrict__ p_oy,
                const int* __restrict__ p_qmin,
                const int* __restrict__ p_rmin,
                int n4, int dim)
{
    __shared__ int s_lut[2448];   // 49*49 = 2401

    for (int i = threadIdx.x; i < dim * dim; i += blockDim.x)
        s_lut[i] = lut[i];

    float hs  = *p_hs;
    float rot = *p_rot;
    float ox  = *p_ox;
    float oy  = *p_oy;
    int qmin  = *p_qmin;
    int rmin  = *p_rmin;

    float ca = cosf(-rot), sa = sinf(-rot);
    float inv_hs = 1.0f / hs;
    float c1 = 0.57735026919f * inv_hs;          // (sqrt3/3)/hs
    float c2 = -0.33333333333f * inv_hs;         // -(1/3)/hs
    float c3 = 0.66666666667f * inv_hs;          // (2/3)/hs

    __syncthreads();

    float* my_col = g_scratch + blockIdx.x;      // this CTA's private column

    const float4* x4 = reinterpret_cast<const float4*>(x);
    const float4* y4 = reinterpret_cast<const float4*>(y);
    const float4* v4 = reinterpret_cast<const float4*>(vals);

    int stride = gridDim.x * blockDim.x;
    for (int i = blockIdx.x * blockDim.x + threadIdx.x; i < n4; i += stride) {
        float4 xx = x4[i];
        float4 yy = y4[i];
        float4 vv = v4[i];
        photon_one(xx.x, yy.x, vv.x, ca, sa, ox, oy, c1, c2, c3,
                   qmin, rmin, dim, s_lut, my_col);
        photon_one(xx.y, yy.y, vv.y, ca, sa, ox, oy, c1, c2, c3,
                   qmin, rmin, dim, s_lut, my_col);
        photon_one(xx.z, yy.z, vv.z, ca, sa, ox, oy, c1, c2, c3,
                   qmin, rmin, dim, s_lut, my_col);
        photon_one(xx.w, yy.w, vv.w, ca, sa, ox, oy, c1, c2, c3,
                   qmin, rmin, dim, s_lut, my_col);
    }
}

// ---------------------- reduce stage 1: warp per (pix, quarter) ------------
__global__ __launch_bounds__(256)
void reduce1_kernel(int ntasks) {
    int task = (blockIdx.x * blockDim.x + threadIdx.x) >> 5;   // global warp id
    int lane = threadIdx.x & 31;
    if (task >= ntasks) return;
    int pix     = task >> 2;
    int quarter = task & 3;
    const float* row = g_scratch + (size_t)pix * NCTA + quarter * QUARTER;

    float s = 0.f;
    // 148 floats per quarter: lanes stride 32 (4-5 each, coalesced)
    #pragma unroll
    for (int j = lane; j < QUARTER; j += 32)
        s += row[j];

    #pragma unroll
    for (int off = 16; off > 0; off >>= 1)
        s += __shfl_down_sync(0xFFFFFFFFu, s, off);

    if (lane == 0)
        g_partial[task] = s;
}

// ---------------------- reduce stage 2: 4 partials -> out ------------------
__global__ void reduce2_kernel(float* __restrict__ out, int npix) {
    int p = blockIdx.x * blockDim.x + threadIdx.x;
    if (p >= npix) return;
    float4 t = reinterpret_cast<const float4*>(g_partial)[p];
    out[p] = (t.x + t.y) + (t.z + t.w);
}

// ------------------------------ launch -------------------------------------
extern "C" void kernel_launch(void* const* d_in, const int* in_sizes, int n_in,
                              void* d_out, int out_size)
{
    const float* x    = (const float*)d_in[0];
    const float* y    = (const float*)d_in[1];
    const float* vals = (const float*)d_in[2];
    const int*   lut  = (const int*)  d_in[3];
    const float* hs   = (const float*)d_in[4];
    const float* rot  = (const float*)d_in[5];
    const float* ox   = (const float*)d_in[6];
    const float* oy   = (const float*)d_in[7];
    const int*   qmin = (const int*)  d_in[8];
    const int*   rmin = (const int*)  d_in[9];

    int n = in_sizes[0];
    int lutsize = in_sizes[3];
    int dim = 1;
    while (dim * dim < lutsize) dim++;   // 49

    int npix = out_size;                 // 1801
    if (npix > MAX_PIX) npix = MAX_PIX;

    int total4 = (npix * NCTA) / 4;
    zero_kernel<<<592, 256>>>(total4);
    hex_kernel<<<NCTA, TPB>>>(x, y, vals, lut, hs, rot, ox, oy,
                              qmin, rmin, n / 4, dim);
    int ntasks = npix * 4;               // 7204 warps
    int nblk = (ntasks * 32 + 255) / 256;
    reduce1_kernel<<<nblk, 256>>>(ntasks);
    reduce2_kernel<<<(npix + 127) / 128, 128>>>((float*)d_out, npix);
}

// round 7
// speedup vs baseline: 1.6675x; 1.0255x over previous
#include <cuda_runtime.h>
#include <cstdint>

// ---------------------------------------------------------------------------
// HexagonalSensor: 16.7M photons -> hex-pixel scatter add (1801 bins)
// R5: hybrid atomic backends — half the photons go to a per-CTA smem
// histogram (ATOMS, smem crossbar), half to the per-CTA global column
// (REDG, L2 path). Zeroing fused into hex; single merged warp-per-pixel
// reduce. 2 launches total.
// ---------------------------------------------------------------------------

#define NCTA 592          // 4 CTAs per SM
#define TPB  256
#define MAX_PIX 2048

// scratch[pix * NCTA + cta]  (pix-major so reduce reads contiguous float4s)
__device__ float g_scratch[MAX_PIX * NCTA];

// ------------------------- per-photon pipeline -----------------------------
// USE_SMEM=true  -> accumulate into CTA-private smem histogram (ATOMS)
// USE_SMEM=false -> fire-and-forget REDG into CTA-private global column
template <bool USE_SMEM>
__device__ __forceinline__ void photon_one(
    float x, float y, float v,
    float ca, float sa, float ox, float oy,
    float c1, float c2, float c3,
    int qmin, int rmin, int dim,
    const int* __restrict__ s_lut,
    float* __restrict__ s_hist,
    float* __restrict__ my_col)
{
    // rotate into grid frame
    float xs = x - ox;
    float ys = y - oy;
    float xrot = fmaf(ca, xs, -(sa * ys));
    float yrot = fmaf(sa, xs, ca * ys);

    // cartesian -> axial (constants folded with 1/hex_size)
    float q = fmaf(c1, xrot, c2 * yrot);
    float r = c3 * yrot;
    float s = -q - r;

    // round-half-even via magic add; integer falls out of mantissa bits
    const float MAG = 12582912.0f;           // 1.5 * 2^23
    const int   MAGBITS = 0x4B400000;
    float fq = q + MAG, fr = r + MAG, fs = s + MAG;
    float qr = fq - MAG, rr = fr - MAG, sr = fs - MAG;
    int qi = __float_as_int(fq) - MAGBITS;
    int ri = __float_as_int(fr) - MAGBITS;
    int si = __float_as_int(fs) - MAGBITS;

    // cube-round fixup (faithful to reference _axial_round)
    float qd = fabsf(qr - q), rd = fabsf(rr - r), sd = fabsf(sr - s);
    bool cq = (qd > rd) && (qd > sd);
    bool cr = (rd > qd) && (rd > sd);
    if (cq)      qi = -ri - si;
    else if (cr) ri = -qi - si;

    int q_idx = qi - qmin;
    int r_idx = ri - rmin;
    bool inb = ((unsigned)q_idx < (unsigned)dim) &
               ((unsigned)r_idx < (unsigned)dim);
    int pix = -1;
    if (inb) pix = s_lut[q_idx * dim + r_idx];
    if (pix >= 0) {
        if (USE_SMEM)
            atomicAdd(&s_hist[pix], v);                       // ATOMS.ADD.F32
        else
            atomicAdd(my_col + (size_t)pix * NCTA, v);        // RED.E.ADD.F32
    }
}

__global__ __launch_bounds__(TPB)
void hex_kernel(const float* __restrict__ x,
                const float* __restrict__ y,
                const float* __restrict__ vals,
                const int* __restrict__ lut,
                const float* __restrict__ p_hs,
                const float* __restrict__ p_rot,
                const float* __restrict__ p_ox,
                const float* __restrict__ p_oy,
                const int* __restrict__ p_qmin,
                const int* __restrict__ p_rmin,
                int n4, int dim, int npix)
{
    __shared__ int   s_lut[2416];    // 49*49 = 2401
    __shared__ float s_hist[1804];   // per-CTA private histogram

    float* my_col = g_scratch + blockIdx.x;   // per-CTA private global column

    // --- fused zero: this CTA's scratch column + smem histogram ---
    for (int p = threadIdx.x; p < npix; p += TPB) {
        my_col[(unsigned)p * NCTA] = 0.0f;
        s_hist[p] = 0.0f;
    }
    for (int i = threadIdx.x; i < dim * dim; i += TPB)
        s_lut[i] = lut[i];

    float hs  = *p_hs;
    float rot = *p_rot;
    float ox  = *p_ox;
    float oy  = *p_oy;
    int qmin  = *p_qmin;
    int rmin  = *p_rmin;

    float ca = cosf(-rot), sa = sinf(-rot);
    float inv_hs = 1.0f / hs;
    float c1 = 0.57735026919f * inv_hs;          // (sqrt3/3)/hs
    float c2 = -0.33333333333f * inv_hs;         // -(1/3)/hs
    float c3 = 0.66666666667f * inv_hs;          // (2/3)/hs

    __threadfence();      // column zeros visible before any REDG lands
    __syncthreads();

    const float4* x4 = reinterpret_cast<const float4*>(x);
    const float4* y4 = reinterpret_cast<const float4*>(y);
    const float4* v4 = reinterpret_cast<const float4*>(vals);

    int stride = gridDim.x * blockDim.x;
    for (int i = blockIdx.x * blockDim.x + threadIdx.x; i < n4; i += stride) {
        float4 xx = x4[i];
        float4 yy = y4[i];
        float4 vv = v4[i];
        // alternate backends: .x,.z -> smem ATOMS ; .y,.w -> global REDG
        photon_one<true >(xx.x, yy.x, vv.x, ca, sa, ox, oy, c1, c2, c3,
                          qmin, rmin, dim, s_lut, s_hist, my_col);
        photon_one<false>(xx.y, yy.y, vv.y, ca, sa, ox, oy, c1, c2, c3,
                          qmin, rmin, dim, s_lut, s_hist, my_col);
        photon_one<true >(xx.z, yy.z, vv.z, ca, sa, ox, oy, c1, c2, c3,
                          qmin, rmin, dim, s_lut, s_hist, my_col);
        photon_one<false>(xx.w, yy.w, vv.w, ca, sa, ox, oy, c1, c2, c3,
                          qmin, rmin, dim, s_lut, s_hist, my_col);
    }

    // --- flush smem histogram into this CTA's global column ---
    __syncthreads();
    for (int p = threadIdx.x; p < npix; p += TPB) {
        float v = s_hist[p];
        if (v != 0.0f)
            atomicAdd(my_col + (unsigned)p * NCTA, v);  // own REDGs may still
    }                                                   // be in flight -> RED
}

// ---------------- merged reduce: one warp per pixel ------------------------
__global__ __launch_bounds__(256)
void reduce_kernel(float* __restrict__ out, int npix) {
    int pix  = (blockIdx.x * blockDim.x + threadIdx.x) >> 5;
    int lane = threadIdx.x & 31;
    if (pix >= npix) return;

    const float4* row = reinterpret_cast<const float4*>(
        g_scratch + (size_t)pix * NCTA);          // NCTA/4 = 148 float4s

    float s0 = 0.f, s1 = 0.f, s2 = 0.f, s3 = 0.f;
    for (int j = lane; j < NCTA / 4; j += 32) {
        float4 t = row[j];
        s0 += t.x; s1 += t.y; s2 += t.z; s3 += t.w;
    }
    float s = (s0 + s1) + (s2 + s3);
    #pragma unroll
    for (int off = 16; off > 0; off >>= 1)
        s += __shfl_down_sync(0xFFFFFFFFu, s, off);
    if (lane == 0)
        out[pix] = s;
}

// ------------------------------ launch -------------------------------------
extern "C" void kernel_launch(void* const* d_in, const int* in_sizes, int n_in,
                              void* d_out, int out_size)
{
    const float* x    = (const float*)d_in[0];
    const float* y    = (const float*)d_in[1];
    const float* vals = (const float*)d_in[2];
    const int*   lut  = (const int*)  d_in[3];
    const float* hs   = (const float*)d_in[4];
    const float* rot  = (const float*)d_in[5];
    const float* ox   = (const float*)d_in[6];
    const float* oy   = (const float*)d_in[7];
    const int*   qmin = (const int*)  d_in[8];
    const int*   rmin = (const int*)  d_in[9];

    int n = in_sizes[0];
    int lutsize = in_sizes[3];
    int dim = 1;
    while (dim * dim < lutsize) dim++;   // 49

    int npix = out_size;                 // 1801
    if (npix > MAX_PIX) npix = MAX_PIX;

    hex_kernel<<<NCTA, TPB>>>(x, y, vals, lut, hs, rot, ox, oy,
                              qmin, rmin, n / 4, dim, npix);
    int nblk = (npix * 32 + 255) / 256;  // one warp per pixel
    reduce_kernel<<<nblk, 256>>>((float*)d_out, npix);
}